// round 3
// baseline (speedup 1.0000x reference)
#include <cuda_runtime.h>
#include <math.h>

typedef unsigned long long ull;

// ---------------- f32x2 packed-math helpers (sm_103a) ----------------
__device__ __forceinline__ ull fma2(ull a, ull b, ull c){
    ull d; asm("fma.rn.f32x2 %0, %1, %2, %3;" : "=l"(d) : "l"(a), "l"(b), "l"(c)); return d;
}
__device__ __forceinline__ ull pack2(float x){
    ull r; asm("mov.b64 %0, {%1, %1};" : "=l"(r) : "f"(x)); return r;
}
__device__ __forceinline__ ull packf2(float a, float b){
    ull r; asm("mov.b64 %0, {%1, %2};" : "=l"(r) : "f"(a), "f"(b)); return r;
}
__device__ __forceinline__ float2 unpack2(ull v){
    float2 r; asm("mov.b64 {%0, %1}, %2;" : "=f"(r.x), "=f"(r.y) : "l"(v)); return r;
}

// ---------------- scratch (device globals; no allocations allowed) ----------------
#define MAXN 50048
#define MAXE 800000

__device__ float g_xl[MAXN * 256];
__device__ float g_xr[MAXN * 256];
__device__ float g_h1[MAXN * 128];
__device__ float g_h2[MAXN * 128];
__device__ float g_h3[MAXN * 64];
__device__ float g_mattr[MAXN * 16];
__device__ float g_gvec[64 * 64];
__device__ int   g_deg[MAXN + 1];
__device__ int   g_rowptr[MAXN + 1];
__device__ int   g_cursor[MAXN];
__device__ int2  g_se[MAXE];

// ---------------- prep kernels ----------------
__global__ void zero_k(int* __restrict__ deg, int n){
    int t = blockIdx.x * blockDim.x + threadIdx.x;
    if (t < n + 1) deg[t] = 0;
}

__global__ void deg_k(const int* __restrict__ dst, int* __restrict__ deg, int E){
    int e = blockIdx.x * blockDim.x + threadIdx.x;
    if (e < E) atomicAdd(&deg[dst[e]], 1);
}

// single-block exclusive scan of deg -> rowptr (and cursor copy)
__global__ void scan_k(const int* __restrict__ deg, int* __restrict__ rowptr,
                       int* __restrict__ cursor, int n){
    __shared__ int ss[1024];
    int t = threadIdx.x;
    int chunk = (n + 1023) >> 10;
    int s = t * chunk, e = min(s + chunk, n);
    int a = 0;
    for (int i = s; i < e; i++) a += deg[i];
    ss[t] = a; __syncthreads();
    for (int ofs = 1; ofs < 1024; ofs <<= 1){
        int v = (t >= ofs) ? ss[t - ofs] : 0;
        __syncthreads();
        ss[t] += v;
        __syncthreads();
    }
    int run = (t == 0) ? 0 : ss[t - 1];
    for (int i = s; i < e; i++){ rowptr[i] = run; cursor[i] = run; run += deg[i]; }
    if (t == 1023) rowptr[n] = ss[1023];
}

__global__ void scatter_k(const int* __restrict__ src, const int* __restrict__ dst,
                          int* __restrict__ cursor, int2* __restrict__ se, int E){
    int e = blockIdx.x * blockDim.x + threadIdx.x;
    if (e >= E) return;
    int d = dst[e];
    int slot = atomicAdd(&cursor[d], 1);
    se[slot] = make_int2(src[e], e);
}

// mean edge attr per node from CSR (no atomics)
__global__ void mattr_k(const float* __restrict__ eattr, const int2* __restrict__ se,
                        const int* __restrict__ rowptr, float* __restrict__ mattr, int n){
    int t = blockIdx.x * blockDim.x + threadIdx.x;
    int node = t >> 2, q = t & 3;
    if (node >= n) return;
    int a = rowptr[node], b = rowptr[node + 1];
    float4 s = make_float4(0.f, 0.f, 0.f, 0.f);
    for (int i = a; i < b; i++){
        int eid = __ldg(&se[i]).y;
        float4 v = __ldg((const float4*)(eattr + (size_t)eid * 16 + q * 4));
        s.x += v.x; s.y += v.y; s.z += v.z; s.w += v.w;
    }
    float inv = 1.f / (float)max(b - a, 1);
    s.x *= inv; s.y *= inv; s.z *= inv; s.w *= inv;
    *(float4*)(mattr + (size_t)node * 16 + q * 4) = s;
}

// ---------------- fused dual GEMM: Ya=X@Wa+Ba, Yb=X@Wb+Bb (blockIdx.z picks) ----
// block: 256 thr = 32 tx (cols, TN=4) x 8 ty (row groups, TM=8). BM=64, BN=128, BK=16.
template<int COUT>
__global__ void __launch_bounds__(256) gemm2(const float* __restrict__ X,
                                             const float* __restrict__ Wa,
                                             const float* __restrict__ Ba,
                                             const float* __restrict__ Wb,
                                             const float* __restrict__ Bb,
                                             float* __restrict__ Ya,
                                             float* __restrict__ Yb, int n){
    const float* W = blockIdx.z ? Wb : Wa;
    const float* B = blockIdx.z ? Bb : Ba;
    float*       Y = blockIdx.z ? Yb : Ya;

    __shared__ float sxT[128 * 68];   // x transposed: [k][row], padded stride 68
    __shared__ float sw[16 * 128];
    int t = threadIdx.x;
    int tx = t & 31, ty = t >> 5;
    int row0 = blockIdx.y * 64;
    int cb   = blockIdx.x * 128;

    #pragma unroll
    for (int i = 0; i < 8; i++){
        int f = t + 256 * i;
        int r = f >> 5, c4 = f & 31;
        float4 v = make_float4(0.f, 0.f, 0.f, 0.f);
        if (row0 + r < n) v = __ldg((const float4*)(X + (size_t)(row0 + r) * 128 + c4 * 4));
        sxT[(c4 * 4 + 0) * 68 + r] = v.x;
        sxT[(c4 * 4 + 1) * 68 + r] = v.y;
        sxT[(c4 * 4 + 2) * 68 + r] = v.z;
        sxT[(c4 * 4 + 3) * 68 + r] = v.w;
    }

    ull acc[8][2];
    #pragma unroll
    for (int r = 0; r < 8; r++){ acc[r][0] = 0ull; acc[r][1] = 0ull; }

    #pragma unroll 1
    for (int kt = 0; kt < 8; kt++){
        __syncthreads();
        #pragma unroll
        for (int i = 0; i < 2; i++){
            int f = t + 256 * i;
            int k = f >> 5, c4 = f & 31;
            *(float4*)&sw[k * 128 + c4 * 4] =
                __ldg((const float4*)(W + (size_t)(kt * 16 + k) * COUT + cb + c4 * 4));
        }
        __syncthreads();
        #pragma unroll
        for (int k = 0; k < 16; k++){
            int kk = kt * 16 + k;
            float4 xa = *(const float4*)&sxT[kk * 68 + ty * 8];
            float4 xb = *(const float4*)&sxT[kk * 68 + ty * 8 + 4];
            float4 wv = *(const float4*)&sw[k * 128 + tx * 4];
            ull w01 = packf2(wv.x, wv.y);
            ull w23 = packf2(wv.z, wv.w);
            float xs[8] = {xa.x, xa.y, xa.z, xa.w, xb.x, xb.y, xb.z, xb.w};
            #pragma unroll
            for (int r = 0; r < 8; r++){
                ull x2 = pack2(xs[r]);
                acc[r][0] = fma2(x2, w01, acc[r][0]);
                acc[r][1] = fma2(x2, w23, acc[r][1]);
            }
        }
    }

    float4 bv = __ldg((const float4*)(B + cb + tx * 4));
    #pragma unroll
    for (int r = 0; r < 8; r++){
        int row = row0 + ty * 8 + r;
        if (row < n){
            float2 p0 = unpack2(acc[r][0]);
            float2 p1 = unpack2(acc[r][1]);
            float4 o = make_float4(p0.x + bv.x, p0.y + bv.y, p1.x + bv.z, p1.y + bv.w);
            *(float4*)(Y + (size_t)row * COUT + cb + tx * 4) = o;
        }
    }
}

// ---------------- fused GATv2 edge pass ----------------
// EPW edges per warp (2 for CH=32: 16 lanes/edge; 1 for CH=64: 32 lanes/edge).
// VPT = 8 channels/lane in both cases. No-max softmax (logits are O(10)).
template<int CH, int EPW, bool MEAN>
__global__ void __launch_bounds__(128) gat_edge(const float* __restrict__ xl,
                                                const float* __restrict__ xr,
                                                const float* __restrict__ We,
                                                const float* __restrict__ att,
                                                const float* __restrict__ bias,
                                                const float* __restrict__ eattr,
                                                const float* __restrict__ mattr,
                                                const int* __restrict__ rowptr,
                                                const int2* __restrict__ se,
                                                float* __restrict__ out, int n){
    constexpr int C   = 4 * CH;
    constexpr int LPE = 32 / EPW;     // lanes per edge
    constexpr int VPT = C / LPE;      // 8
    static_assert(VPT == 8, "VPT must be 8");

    __shared__ float sWe[16 * C];
    for (int i = threadIdx.x; i < 16 * C / 4; i += blockDim.x)
        ((float4*)sWe)[i] = __ldg(((const float4*)We) + i);
    __syncthreads();

    int warp = threadIdx.x >> 5;
    int lane = threadIdx.x & 31;
    int node = blockIdx.x * 4 + warp;
    if (node >= n) return;

    int esel = (EPW == 2) ? (lane >> 4) : 0;
    int sub  = lane & (LPE - 1);

    float atv[8], xrv[8];
    #pragma unroll
    for (int p = 0; p < 2; p++){
        *(float4*)&atv[p * 4] = __ldg((const float4*)(att + sub * 8 + p * 4));
        *(float4*)&xrv[p * 4] = __ldg((const float4*)(xr + (size_t)node * C + sub * 8 + p * 4));
    }

    float l = 0.f;
    float acc[8];
    #pragma unroll
    for (int j = 0; j < 8; j++) acc[j] = 0.f;

    const int start = rowptr[node], endi = rowptr[node + 1]; // endi == self-loop slot

    for (int base = start; base <= endi; base += EPW){
        int idx = base + esel;
        bool valid = (idx <= endi);
        int s; const float* ea;
        if (idx < endi){
            int2 pr = __ldg(se + idx);
            s = pr.x; ea = eattr + (size_t)pr.y * 16;
        } else {
            s = node; ea = mattr + (size_t)node * 16;  // self loop (or invalid: p=0)
        }

        float aa[16];
        #pragma unroll
        for (int p = 0; p < 4; p++)
            *(float4*)&aa[p * 4] = __ldg((const float4*)(ea + p * 4));

        float xv[8];
        const float* xp = xl + (size_t)s * C + sub * 8;
        #pragma unroll
        for (int p = 0; p < 2; p++)
            *(float4*)&xv[p * 4] = __ldg((const float4*)(xp + p * 4));

        // ee = ea @ We : packed f32x2, LDS.128 via ulonglong2
        ull e2[4];
        #pragma unroll
        for (int j = 0; j < 4; j++) e2[j] = 0ull;
        #pragma unroll
        for (int k = 0; k < 16; k++){
            ull a2 = pack2(aa[k]);
            const ulonglong2* wp = (const ulonglong2*)(sWe + k * C + sub * 8);
            ulonglong2 w0 = wp[0], w1 = wp[1];
            e2[0] = fma2(a2, w0.x, e2[0]);
            e2[1] = fma2(a2, w0.y, e2[1]);
            e2[2] = fma2(a2, w1.x, e2[2]);
            e2[3] = fma2(a2, w1.y, e2[3]);
        }

        // logit = sum_c leaky_relu(xl+xr+ee) * att   (leaky = max(z, 0.2z))
        float part = 0.f;
        #pragma unroll
        for (int j = 0; j < 4; j++){
            float2 ez = unpack2(e2[j]);
            float z0 = xv[2 * j]     + xrv[2 * j]     + ez.x;
            float z1 = xv[2 * j + 1] + xrv[2 * j + 1] + ez.y;
            z0 = fmaxf(z0, 0.2f * z0);
            z1 = fmaxf(z1, 0.2f * z1);
            part = fmaf(z0, atv[2 * j], part);
            part = fmaf(z1, atv[2 * j + 1], part);
        }
        part += __shfl_xor_sync(0xffffffffu, part, 1);
        part += __shfl_xor_sync(0xffffffffu, part, 2);
        if (CH == 64) part += __shfl_xor_sync(0xffffffffu, part, 4);

        float p = valid ? __expf(part) : 0.f;
        l += p;
        ull p2 = pack2(p);
        ull* acc2 = (ull*)acc;
        ull* xv2  = (ull*)xv;
        #pragma unroll
        for (int j = 0; j < 4; j++) acc2[j] = fma2(p2, xv2[j], acc2[j]);
    }

    if (EPW == 2){
        l += __shfl_xor_sync(0xffffffffu, l, 16);
        #pragma unroll
        for (int j = 0; j < 8; j++)
            acc[j] += __shfl_xor_sync(0xffffffffu, acc[j], 16);
    }

    float inv = 1.f / (l + 1e-16f);
    if (!MEAN){
        if (EPW == 1 || lane < 16){
            #pragma unroll
            for (int p = 0; p < 2; p++){
                float4 bo = __ldg((const float4*)(bias + sub * 8 + p * 4));
                float4 o;
                o.x = fmaxf(acc[p * 4 + 0] * inv + bo.x, 0.f);
                o.y = fmaxf(acc[p * 4 + 1] * inv + bo.y, 0.f);
                o.z = fmaxf(acc[p * 4 + 2] * inv + bo.z, 0.f);
                o.w = fmaxf(acc[p * 4 + 3] * inv + bo.w, 0.f);
                *(float4*)(out + (size_t)node * C + sub * 8 + p * 4) = o;
            }
        }
    } else {
        // mean over 4 heads (CH=64, C=256, EPW=1): heads are lane>>3
        float v[8];
        #pragma unroll
        for (int j = 0; j < 8; j++){
            v[j] = acc[j] * inv;
            v[j] += __shfl_xor_sync(0xffffffffu, v[j], 8);
            v[j] += __shfl_xor_sync(0xffffffffu, v[j], 16);
        }
        if (lane < 8){
            #pragma unroll
            for (int p = 0; p < 2; p++){
                float4 bo = __ldg((const float4*)(bias + lane * 8 + p * 4));
                float4 o;
                o.x = fmaxf(0.25f * v[p * 4 + 0] + bo.x, 0.f);
                o.y = fmaxf(0.25f * v[p * 4 + 1] + bo.y, 0.f);
                o.z = fmaxf(0.25f * v[p * 4 + 2] + bo.z, 0.f);
                o.w = fmaxf(0.25f * v[p * 4 + 3] + bo.w, 0.f);
                *(float4*)(out + (size_t)node * CH + lane * 8 + p * 4) = o;
            }
        }
    }
}

// ---------------- global mean pool (batch is sorted; one block per graph) ----------------
__device__ __forceinline__ int lowerb(const int* a, int n, int v){
    int lo = 0, hi = n;
    while (lo < hi){ int md = (lo + hi) >> 1; if (a[md] < v) lo = md + 1; else hi = md; }
    return lo;
}

__global__ void pool_k(const float* __restrict__ h3, const int* __restrict__ batch,
                       float* __restrict__ gvec, int n){
    int g = blockIdx.x;
    int lo = lowerb(batch, n, g), hi = lowerb(batch, n, g + 1);
    int t = threadIdx.x;
    int ch = t & 63, rr = t >> 6;
    float s = 0.f;
    for (int i = lo + rr; i < hi; i += 4) s += h3[(size_t)i * 64 + ch];
    __shared__ float red[4][64];
    red[rr][ch] = s; __syncthreads();
    if (rr == 0){
        float tot = red[0][ch] + red[1][ch] + red[2][ch] + red[3][ch];
        float c = (float)max(hi - lo, 1);
        gvec[g * 64 + ch] = tot / c;
    }
}

__global__ void final_k(const float* __restrict__ gvec, const float* __restrict__ Wlin,
                        const float* __restrict__ blin, float* __restrict__ out){
    int t = threadIdx.x;
    int g = t >> 4, o = t & 15;
    float s = 0.f;
    #pragma unroll
    for (int k = 0; k < 64; k++) s = fmaf(gvec[g * 64 + k], Wlin[k * 16 + o], s);
    out[t] = s + blin[o];
}

// ---------------- host orchestration ----------------
extern "C" void kernel_launch(void* const* d_in, const int* in_sizes, int n_in,
                              void* d_out, int out_size){
    const float* x     = (const float*)d_in[0];
    const int*   eidx  = (const int*)  d_in[1];
    const int*   batch = (const int*)  d_in[2];
    const float* eattr = (const float*)d_in[3];
    const float* Wl0 = (const float*)d_in[4],  *bl0 = (const float*)d_in[5];
    const float* Wr0 = (const float*)d_in[6],  *br0 = (const float*)d_in[7];
    const float* We0 = (const float*)d_in[8],  *att0= (const float*)d_in[9];
    const float* bo0 = (const float*)d_in[10];
    const float* Wlh = (const float*)d_in[11], *blh = (const float*)d_in[12];
    const float* Wrh = (const float*)d_in[13], *brh = (const float*)d_in[14];
    const float* Weh = (const float*)d_in[15], *atth= (const float*)d_in[16];
    const float* boh = (const float*)d_in[17];
    const float* Wlf = (const float*)d_in[18], *blf = (const float*)d_in[19];
    const float* Wrf = (const float*)d_in[20], *brf = (const float*)d_in[21];
    const float* Wef = (const float*)d_in[22], *attf= (const float*)d_in[23];
    const float* bof = (const float*)d_in[24];
    const float* Wlin= (const float*)d_in[25], *blin= (const float*)d_in[26];

    int N = in_sizes[0] / 128;
    int E = in_sizes[1] / 2;
    const int* src = eidx;
    const int* dst = eidx + E;

    float *xl, *xr, *h1, *h2, *h3, *mattr, *gvec;
    int *deg, *rowptr, *cursor;
    int2 *se;
    cudaGetSymbolAddress((void**)&xl,     g_xl);
    cudaGetSymbolAddress((void**)&xr,     g_xr);
    cudaGetSymbolAddress((void**)&h1,     g_h1);
    cudaGetSymbolAddress((void**)&h2,     g_h2);
    cudaGetSymbolAddress((void**)&h3,     g_h3);
    cudaGetSymbolAddress((void**)&mattr,  g_mattr);
    cudaGetSymbolAddress((void**)&gvec,   g_gvec);
    cudaGetSymbolAddress((void**)&deg,    g_deg);
    cudaGetSymbolAddress((void**)&rowptr, g_rowptr);
    cudaGetSymbolAddress((void**)&cursor, g_cursor);
    cudaGetSymbolAddress((void**)&se,     g_se);

    dim3 gA(1, (N + 63) / 64, 2), gB(2, (N + 63) / 64, 2);
    int  eb = (N + 3) / 4;

    // prep chain (gemm_l0 placed at launch idx 3 so ncu -s5 profiles it)
    zero_k   <<<(N + 256) / 256, 256>>>(deg, N);                                   // 0
    deg_k    <<<(E + 255) / 256, 256>>>(dst, deg, E);                              // 1
    scan_k   <<<1, 1024>>>(deg, rowptr, cursor, N);                                // 2
    gemm2<128><<<gA, 256>>>(x, Wl0, bl0, Wr0, br0, xl, xr, N);                     // 3 (profiled)
    scatter_k<<<(E + 255) / 256, 256>>>(src, dst, cursor, se, E);                  // 4
    mattr_k  <<<(N * 4 + 255) / 256, 256>>>(eattr, se, rowptr, mattr, N);          // 5

    // layer 0
    gat_edge<32, 2, false><<<eb, 128>>>(xl, xr, We0, att0, bo0, eattr, mattr,
                                        rowptr, se, h1, N);
    // layer 1
    gemm2<128><<<gA, 256>>>(h1, Wlh, blh, Wrh, brh, xl, xr, N);
    gat_edge<32, 2, false><<<eb, 128>>>(xl, xr, Weh, atth, boh, eattr, mattr,
                                        rowptr, se, h2, N);
    // layer 2 (mean over heads)
    gemm2<256><<<gB, 256>>>(h2, Wlf, blf, Wrf, brf, xl, xr, N);
    gat_edge<64, 1, true><<<eb, 128>>>(xl, xr, Wef, attf, bof, eattr, mattr,
                                       rowptr, se, h3, N);

    // pool + final linear
    pool_k <<<64, 256>>>(h3, batch, gvec, N);
    final_k<<<1, 1024>>>(gvec, Wlin, blin, (float*)d_out);
}

// round 4
// speedup vs baseline: 1.0351x; 1.0351x over previous
#include <cuda_runtime.h>
#include <math.h>

typedef unsigned long long ull;

// ---------------- f32x2 packed-math helpers (sm_103a) ----------------
__device__ __forceinline__ ull fma2(ull a, ull b, ull c){
    ull d; asm("fma.rn.f32x2 %0, %1, %2, %3;" : "=l"(d) : "l"(a), "l"(b), "l"(c)); return d;
}
__device__ __forceinline__ ull pack2(float x){
    ull r; asm("mov.b64 %0, {%1, %1};" : "=l"(r) : "f"(x)); return r;
}
__device__ __forceinline__ ull packf2(float a, float b){
    ull r; asm("mov.b64 %0, {%1, %2};" : "=l"(r) : "f"(a), "f"(b)); return r;
}
__device__ __forceinline__ float2 unpack2(ull v){
    float2 r; asm("mov.b64 {%0, %1}, %2;" : "=f"(r.x), "=f"(r.y) : "l"(v)); return r;
}

// ---------------- scratch (device globals; no allocations allowed) ----------------
#define MAXN 50048
#define MAXE 800000

__device__ float g_xl[MAXN * 256];
__device__ float g_xr[MAXN * 256];
__device__ float g_h1[MAXN * 128];
__device__ float g_h2[MAXN * 128];
__device__ float g_h3[MAXN * 64];
__device__ float g_gvec[64 * 64];
__device__ int   g_rowptr[MAXN + 1];
__device__ int   g_cursor[MAXN];
__device__ int2  g_se[MAXE];

// ---------------- fused degree histogram + exclusive scan (single block) ------
// deg lives in dynamic smem ((n+1)*4 bytes, ~196KB); scan buffer after it.
__global__ void degscan_k(const int* __restrict__ dst, int E, int n,
                          int* __restrict__ rowptr, int* __restrict__ cursor){
    extern __shared__ int sh[];           // [0..n] deg, [n+1 .. n+1024] scan buf
    int* sdeg = sh;
    int* sbuf = sh + n + 1;
    int t = threadIdx.x;

    for (int i = t; i <= n; i += 1024) sdeg[i] = 0;
    __syncthreads();
    for (int e = t; e < E; e += 1024) atomicAdd(&sdeg[dst[e]], 1);
    __syncthreads();

    int chunk = (n + 1023) >> 10;
    int s = t * chunk, e = min(s + chunk, n);
    int a = 0;
    for (int i = s; i < e; i++) a += sdeg[i];
    sbuf[t] = a; __syncthreads();
    for (int ofs = 1; ofs < 1024; ofs <<= 1){
        int v = (t >= ofs) ? sbuf[t - ofs] : 0;
        __syncthreads();
        sbuf[t] += v;
        __syncthreads();
    }
    int run = (t == 0) ? 0 : sbuf[t - 1];
    for (int i = s; i < e; i++){
        rowptr[i] = run; cursor[i] = run; run += sdeg[i];
    }
    if (t == 1023) rowptr[n] = sbuf[1023];
}

__global__ void scatter_k(const int* __restrict__ src, const int* __restrict__ dst,
                          int* __restrict__ cursor, int2* __restrict__ se, int E){
    int e = blockIdx.x * blockDim.x + threadIdx.x;
    if (e >= E) return;
    int d = dst[e];
    int slot = atomicAdd(&cursor[d], 1);
    se[slot] = make_int2(src[e], e);
}

// ---------------- fused dual GEMM: Ya=X@Wa+Ba, Yb=X@Wb+Bb (blockIdx.z picks) ----
template<int COUT>
__global__ void __launch_bounds__(256) gemm2(const float* __restrict__ X,
                                             const float* __restrict__ Wa,
                                             const float* __restrict__ Ba,
                                             const float* __restrict__ Wb,
                                             const float* __restrict__ Bb,
                                             float* __restrict__ Ya,
                                             float* __restrict__ Yb, int n){
    const float* W = blockIdx.z ? Wb : Wa;
    const float* B = blockIdx.z ? Bb : Ba;
    float*       Y = blockIdx.z ? Yb : Ya;

    __shared__ float sxT[128 * 68];
    __shared__ float sw[16 * 128];
    int t = threadIdx.x;
    int tx = t & 31, ty = t >> 5;
    int row0 = blockIdx.y * 64;
    int cb   = blockIdx.x * 128;

    #pragma unroll
    for (int i = 0; i < 8; i++){
        int f = t + 256 * i;
        int r = f >> 5, c4 = f & 31;
        float4 v = make_float4(0.f, 0.f, 0.f, 0.f);
        if (row0 + r < n) v = __ldg((const float4*)(X + (size_t)(row0 + r) * 128 + c4 * 4));
        sxT[(c4 * 4 + 0) * 68 + r] = v.x;
        sxT[(c4 * 4 + 1) * 68 + r] = v.y;
        sxT[(c4 * 4 + 2) * 68 + r] = v.z;
        sxT[(c4 * 4 + 3) * 68 + r] = v.w;
    }

    ull acc[8][2];
    #pragma unroll
    for (int r = 0; r < 8; r++){ acc[r][0] = 0ull; acc[r][1] = 0ull; }

    #pragma unroll 1
    for (int kt = 0; kt < 8; kt++){
        __syncthreads();
        #pragma unroll
        for (int i = 0; i < 2; i++){
            int f = t + 256 * i;
            int k = f >> 5, c4 = f & 31;
            *(float4*)&sw[k * 128 + c4 * 4] =
                __ldg((const float4*)(W + (size_t)(kt * 16 + k) * COUT + cb + c4 * 4));
        }
        __syncthreads();
        #pragma unroll
        for (int k = 0; k < 16; k++){
            int kk = kt * 16 + k;
            float4 xa = *(const float4*)&sxT[kk * 68 + ty * 8];
            float4 xb = *(const float4*)&sxT[kk * 68 + ty * 8 + 4];
            float4 wv = *(const float4*)&sw[k * 128 + tx * 4];
            ull w01 = packf2(wv.x, wv.y);
            ull w23 = packf2(wv.z, wv.w);
            float xs[8] = {xa.x, xa.y, xa.z, xa.w, xb.x, xb.y, xb.z, xb.w};
            #pragma unroll
            for (int r = 0; r < 8; r++){
                ull x2 = pack2(xs[r]);
                acc[r][0] = fma2(x2, w01, acc[r][0]);
                acc[r][1] = fma2(x2, w23, acc[r][1]);
            }
        }
    }

    float4 bv = __ldg((const float4*)(B + cb + tx * 4));
    #pragma unroll
    for (int r = 0; r < 8; r++){
        int row = row0 + ty * 8 + r;
        if (row < n){
            float2 p0 = unpack2(acc[r][0]);
            float2 p1 = unpack2(acc[r][1]);
            float4 o = make_float4(p0.x + bv.x, p0.y + bv.y, p1.x + bv.z, p1.y + bv.w);
            *(float4*)(Y + (size_t)row * COUT + cb + tx * 4) = o;
        }
    }
}

// ---------------- fused GATv2 edge pass: one warp per dst node ----------------
// EPW=1 (R1 config, measured best). Self-loop mean-attr computed on the fly
// (running sum of incoming edge attrs), so no mattr kernel/array is needed.
// No-max softmax (logits are O(10)); exp2 with ln2 folded into att.
template<int CH, bool MEAN>
__global__ void __launch_bounds__(256) gat_edge(const float* __restrict__ xl,
                                                const float* __restrict__ xr,
                                                const float* __restrict__ We,
                                                const float* __restrict__ att,
                                                const float* __restrict__ bias,
                                                const float* __restrict__ eattr,
                                                const int* __restrict__ rowptr,
                                                const int2* __restrict__ se,
                                                float* __restrict__ out, int n){
    constexpr int C   = 4 * CH;
    constexpr int VPT = C / 32;       // 4 (CH=32) or 8 (CH=64)
    constexpr int NP  = VPT / 4;

    __shared__ float sWe[16 * C];
    for (int i = threadIdx.x; i < 16 * C / 4; i += blockDim.x)
        ((float4*)sWe)[i] = __ldg(((const float4*)We) + i);
    __syncthreads();

    int warp = threadIdx.x >> 5;
    int lane = threadIdx.x & 31;
    int node = blockIdx.x * 8 + warp;
    if (node >= n) return;

    float atv[VPT], xrv[VPT];
    #pragma unroll
    for (int p = 0; p < NP; p++){
        float4 av = __ldg((const float4*)(att + lane * VPT + p * 4));
        av.x *= 1.4426950408889634f; av.y *= 1.4426950408889634f;
        av.z *= 1.4426950408889634f; av.w *= 1.4426950408889634f;
        *(float4*)&atv[p * 4] = av;
        *(float4*)&xrv[p * 4] = __ldg((const float4*)(xr + (size_t)node * C + lane * VPT + p * 4));
    }

    float l = 0.f;
    float acc[VPT], sa[16];
    #pragma unroll
    for (int j = 0; j < VPT; j++) acc[j] = 0.f;
    #pragma unroll
    for (int j = 0; j < 16; j++) sa[j] = 0.f;

    const int start = rowptr[node], endi = rowptr[node + 1];
    const float* wbase = sWe + lane * VPT;

    auto BODY = [&](const float (&aa)[16], const float (&xv)[VPT]){
        ull e2[VPT / 2];
        #pragma unroll
        for (int j = 0; j < VPT / 2; j++) e2[j] = 0ull;
        #pragma unroll
        for (int k = 0; k < 16; k++){
            ull a2 = pack2(aa[k]);
            const ulonglong2* wp = (const ulonglong2*)(wbase + k * C);
            #pragma unroll
            for (int np = 0; np < NP; np++){
                ulonglong2 w = wp[np];
                e2[2 * np]     = fma2(a2, w.x, e2[2 * np]);
                e2[2 * np + 1] = fma2(a2, w.y, e2[2 * np + 1]);
            }
        }
        float part = 0.f;
        #pragma unroll
        for (int j = 0; j < VPT / 2; j++){
            float2 ez = unpack2(e2[j]);
            float z0 = xv[2 * j]     + xrv[2 * j]     + ez.x;
            float z1 = xv[2 * j + 1] + xrv[2 * j + 1] + ez.y;
            z0 = fmaxf(z0, 0.2f * z0);
            z1 = fmaxf(z1, 0.2f * z1);
            part = fmaf(z0, atv[2 * j], part);
            part = fmaf(z1, atv[2 * j + 1], part);
        }
        part += __shfl_xor_sync(0xffffffffu, part, 1);
        part += __shfl_xor_sync(0xffffffffu, part, 2);
        part += __shfl_xor_sync(0xffffffffu, part, 4);
        float p = exp2f(part);
        l += p;
        ull p2 = pack2(p);
        ull* acc2 = (ull*)acc;
        const ull* xv2 = (const ull*)xv;
        #pragma unroll
        for (int j = 0; j < VPT / 2; j++) acc2[j] = fma2(p2, xv2[j], acc2[j]);
    };

    for (int i = start; i < endi; i++){
        int2 pr = __ldg(se + i);
        float aa[16];
        const float* ea = eattr + (size_t)pr.y * 16;
        #pragma unroll
        for (int p = 0; p < 4; p++)
            *(float4*)&aa[p * 4] = __ldg((const float4*)(ea + p * 4));
        #pragma unroll
        for (int j = 0; j < 16; j++) sa[j] += aa[j];

        float xv[VPT];
        const float* xp = xl + (size_t)pr.x * C + lane * VPT;
        #pragma unroll
        for (int p = 0; p < NP; p++)
            *(float4*)&xv[p * 4] = __ldg((const float4*)(xp + p * 4));

        BODY(aa, xv);
    }

    // self loop: mean of incoming attrs, xl of self
    {
        float invd = 1.f / (float)max(endi - start, 1);
        float aa[16];
        #pragma unroll
        for (int j = 0; j < 16; j++) aa[j] = sa[j] * invd;
        float xv[VPT];
        const float* xp = xl + (size_t)node * C + lane * VPT;
        #pragma unroll
        for (int p = 0; p < NP; p++)
            *(float4*)&xv[p * 4] = __ldg((const float4*)(xp + p * 4));
        BODY(aa, xv);
    }

    float inv = 1.f / (l + 1e-16f);
    if (!MEAN){
        #pragma unroll
        for (int p = 0; p < NP; p++){
            float4 bo = __ldg((const float4*)(bias + lane * VPT + p * 4));
            float4 o;
            o.x = fmaxf(acc[p * 4 + 0] * inv + bo.x, 0.f);
            o.y = fmaxf(acc[p * 4 + 1] * inv + bo.y, 0.f);
            o.z = fmaxf(acc[p * 4 + 2] * inv + bo.z, 0.f);
            o.w = fmaxf(acc[p * 4 + 3] * inv + bo.w, 0.f);
            *(float4*)(out + (size_t)node * C + lane * VPT + p * 4) = o;
        }
    } else {
        float v[VPT];
        #pragma unroll
        for (int j = 0; j < VPT; j++){
            v[j] = acc[j] * inv;
            v[j] += __shfl_xor_sync(0xffffffffu, v[j], 8);
            v[j] += __shfl_xor_sync(0xffffffffu, v[j], 16);
        }
        if (lane < 8){
            #pragma unroll
            for (int p = 0; p < NP; p++){
                float4 bo = __ldg((const float4*)(bias + lane * VPT + p * 4));
                float4 o;
                o.x = fmaxf(0.25f * v[p * 4 + 0] + bo.x, 0.f);
                o.y = fmaxf(0.25f * v[p * 4 + 1] + bo.y, 0.f);
                o.z = fmaxf(0.25f * v[p * 4 + 2] + bo.z, 0.f);
                o.w = fmaxf(0.25f * v[p * 4 + 3] + bo.w, 0.f);
                *(float4*)(out + (size_t)node * CH + lane * VPT + p * 4) = o;
            }
        }
    }
}

// ---------------- global mean pool (batch is sorted; one block per graph) ----------------
__device__ __forceinline__ int lowerb(const int* a, int n, int v){
    int lo = 0, hi = n;
    while (lo < hi){ int md = (lo + hi) >> 1; if (a[md] < v) lo = md + 1; else hi = md; }
    return lo;
}

__global__ void pool_k(const float* __restrict__ h3, const int* __restrict__ batch,
                       float* __restrict__ gvec, int n){
    int g = blockIdx.x;
    int lo = lowerb(batch, n, g), hi = lowerb(batch, n, g + 1);
    int t = threadIdx.x;
    int ch = t & 63, rr = t >> 6;
    float s = 0.f;
    for (int i = lo + rr; i < hi; i += 4) s += h3[(size_t)i * 64 + ch];
    __shared__ float red[4][64];
    red[rr][ch] = s; __syncthreads();
    if (rr == 0){
        float tot = red[0][ch] + red[1][ch] + red[2][ch] + red[3][ch];
        float c = (float)max(hi - lo, 1);
        gvec[g * 64 + ch] = tot / c;
    }
}

__global__ void final_k(const float* __restrict__ gvec, const float* __restrict__ Wlin,
                        const float* __restrict__ blin, float* __restrict__ out){
    int t = threadIdx.x;
    int g = t >> 4, o = t & 15;
    float s = 0.f;
    #pragma unroll
    for (int k = 0; k < 64; k++) s = fmaf(gvec[g * 64 + k], Wlin[k * 16 + o], s);
    out[t] = s + blin[o];
}

// ---------------- host orchestration ----------------
extern "C" void kernel_launch(void* const* d_in, const int* in_sizes, int n_in,
                              void* d_out, int out_size){
    const float* x     = (const float*)d_in[0];
    const int*   eidx  = (const int*)  d_in[1];
    const int*   batch = (const int*)  d_in[2];
    const float* eattr = (const float*)d_in[3];
    const float* Wl0 = (const float*)d_in[4],  *bl0 = (const float*)d_in[5];
    const float* Wr0 = (const float*)d_in[6],  *br0 = (const float*)d_in[7];
    const float* We0 = (const float*)d_in[8],  *att0= (const float*)d_in[9];
    const float* bo0 = (const float*)d_in[10];
    const float* Wlh = (const float*)d_in[11], *blh = (const float*)d_in[12];
    const float* Wrh = (const float*)d_in[13], *brh = (const float*)d_in[14];
    const float* Weh = (const float*)d_in[15], *atth= (const float*)d_in[16];
    const float* boh = (const float*)d_in[17];
    const float* Wlf = (const float*)d_in[18], *blf = (const float*)d_in[19];
    const float* Wrf = (const float*)d_in[20], *brf = (const float*)d_in[21];
    const float* Wef = (const float*)d_in[22], *attf= (const float*)d_in[23];
    const float* bof = (const float*)d_in[24];
    const float* Wlin= (const float*)d_in[25], *blin= (const float*)d_in[26];

    int N = in_sizes[0] / 128;
    int E = in_sizes[1] / 2;
    const int* src = eidx;
    const int* dst = eidx + E;

    float *xl, *xr, *h1, *h2, *h3, *gvec;
    int *rowptr, *cursor;
    int2 *se;
    cudaGetSymbolAddress((void**)&xl,     g_xl);
    cudaGetSymbolAddress((void**)&xr,     g_xr);
    cudaGetSymbolAddress((void**)&h1,     g_h1);
    cudaGetSymbolAddress((void**)&h2,     g_h2);
    cudaGetSymbolAddress((void**)&h3,     g_h3);
    cudaGetSymbolAddress((void**)&gvec,   g_gvec);
    cudaGetSymbolAddress((void**)&rowptr, g_rowptr);
    cudaGetSymbolAddress((void**)&cursor, g_cursor);
    cudaGetSymbolAddress((void**)&se,     g_se);

    size_t dsmem = (size_t)(N + 1 + 1024) * sizeof(int);
    cudaFuncSetAttribute(degscan_k, cudaFuncAttributeMaxDynamicSharedMemorySize,
                         (int)dsmem);

    dim3 gA(1, (N + 63) / 64, 2), gB(2, (N + 63) / 64, 2);
    int  eb = (N + 7) / 8;

    // launch order chosen so gat_edge layer 0 is kernel-launch index 3 (profiled)
    degscan_k<<<1, 1024, dsmem>>>(dst, E, N, rowptr, cursor);                       // 0
    scatter_k<<<(E + 255) / 256, 256>>>(src, dst, cursor, se, E);                   // 1
    gemm2<128><<<gA, 256>>>(x, Wl0, bl0, Wr0, br0, xl, xr, N);                      // 2
    gat_edge<32, false><<<eb, 256>>>(xl, xr, We0, att0, bo0, eattr,
                                     rowptr, se, h1, N);                            // 3 (profiled)
    gemm2<128><<<gA, 256>>>(h1, Wlh, blh, Wrh, brh, xl, xr, N);                     // 4
    gat_edge<32, false><<<eb, 256>>>(xl, xr, Weh, atth, boh, eattr,
                                     rowptr, se, h2, N);                            // 5
    gemm2<256><<<gB, 256>>>(h2, Wlf, blf, Wrf, brf, xl, xr, N);                     // 6
    gat_edge<64, true><<<eb, 256>>>(xl, xr, Wef, attf, bof, eattr,
                                    rowptr, se, h3, N);                             // 7
    pool_k <<<64, 256>>>(h3, batch, gvec, N);                                       // 8
    final_k<<<1, 1024>>>(gvec, Wlin, blin, (float*)d_out);                          // 9
}

// round 5
// speedup vs baseline: 1.5555x; 1.5027x over previous
#include <cuda_runtime.h>
#include <math.h>

typedef unsigned long long ull;

// ---------------- f32x2 packed-math helpers (sm_103a) ----------------
__device__ __forceinline__ ull fma2(ull a, ull b, ull c){
    ull d; asm("fma.rn.f32x2 %0, %1, %2, %3;" : "=l"(d) : "l"(a), "l"(b), "l"(c)); return d;
}
__device__ __forceinline__ ull add2(ull a, ull b){
    ull d; asm("add.rn.f32x2 %0, %1, %2;" : "=l"(d) : "l"(a), "l"(b)); return d;
}
__device__ __forceinline__ ull pack2(float x){
    ull r; asm("mov.b64 %0, {%1, %1};" : "=l"(r) : "f"(x)); return r;
}
__device__ __forceinline__ ull packf2(float a, float b){
    ull r; asm("mov.b64 %0, {%1, %2};" : "=l"(r) : "f"(a), "f"(b)); return r;
}
__device__ __forceinline__ float2 unpack2(ull v){
    float2 r; asm("mov.b64 {%0, %1}, %2;" : "=f"(r.x), "=f"(r.y) : "l"(v)); return r;
}

// ---------------- scratch (device globals; no allocations allowed) ----------------
#define MAXN 50048
#define MAXE 800000

__device__ float g_xl[MAXN * 256];
__device__ float g_xr[MAXN * 256];
__device__ float g_h1[MAXN * 128];
__device__ float g_h2[MAXN * 128];
__device__ float g_h3[MAXN * 64];
__device__ float g_gvec[64 * 64];
__device__ int   g_rowptr[MAXN + 1];
__device__ int   g_cursor[MAXN];
__device__ int2  g_se[MAXE];

// ---------------- fused degree histogram + exclusive scan (single block) ------
__global__ void degscan_k(const int* __restrict__ dst, int E, int n,
                          int* __restrict__ rowptr, int* __restrict__ cursor){
    extern __shared__ int sh[];           // [0..n] deg, [n+1 .. n+1024] scan buf
    int* sdeg = sh;
    int* sbuf = sh + n + 1;
    int t = threadIdx.x;

    for (int i = t; i <= n; i += 1024) sdeg[i] = 0;
    __syncthreads();
    for (int e = t; e < E; e += 1024) atomicAdd(&sdeg[dst[e]], 1);
    __syncthreads();

    int chunk = (n + 1023) >> 10;
    int s = t * chunk, e = min(s + chunk, n);
    int a = 0;
    for (int i = s; i < e; i++) a += sdeg[i];
    sbuf[t] = a; __syncthreads();
    for (int ofs = 1; ofs < 1024; ofs <<= 1){
        int v = (t >= ofs) ? sbuf[t - ofs] : 0;
        __syncthreads();
        sbuf[t] += v;
        __syncthreads();
    }
    int run = (t == 0) ? 0 : sbuf[t - 1];
    for (int i = s; i < e; i++){
        rowptr[i] = run; cursor[i] = run; run += sdeg[i];
    }
    if (t == 1023) rowptr[n] = sbuf[1023];
}

__global__ void scatter_k(const int* __restrict__ src, const int* __restrict__ dst,
                          int* __restrict__ cursor, int2* __restrict__ se, int E){
    int e = blockIdx.x * blockDim.x + threadIdx.x;
    if (e >= E) return;
    int d = dst[e];
    int slot = atomicAdd(&cursor[d], 1);
    se[slot] = make_int2(src[e], e);
}

// ---------------- fused dual GEMM: Ya=X@Wa+Ba, Yb=X@Wb+Bb (blockIdx.z picks) ----
template<int COUT>
__global__ void __launch_bounds__(256) gemm2(const float* __restrict__ X,
                                             const float* __restrict__ Wa,
                                             const float* __restrict__ Ba,
                                             const float* __restrict__ Wb,
                                             const float* __restrict__ Bb,
                                             float* __restrict__ Ya,
                                             float* __restrict__ Yb, int n){
    const float* W = blockIdx.z ? Wb : Wa;
    const float* B = blockIdx.z ? Bb : Ba;
    float*       Y = blockIdx.z ? Yb : Ya;

    __shared__ float sxT[128 * 68];
    __shared__ float sw[16 * 128];
    int t = threadIdx.x;
    int tx = t & 31, ty = t >> 5;
    int row0 = blockIdx.y * 64;
    int cb   = blockIdx.x * 128;

    #pragma unroll
    for (int i = 0; i < 8; i++){
        int f = t + 256 * i;
        int r = f >> 5, c4 = f & 31;
        float4 v = make_float4(0.f, 0.f, 0.f, 0.f);
        if (row0 + r < n) v = __ldg((const float4*)(X + (size_t)(row0 + r) * 128 + c4 * 4));
        sxT[(c4 * 4 + 0) * 68 + r] = v.x;
        sxT[(c4 * 4 + 1) * 68 + r] = v.y;
        sxT[(c4 * 4 + 2) * 68 + r] = v.z;
        sxT[(c4 * 4 + 3) * 68 + r] = v.w;
    }

    ull acc[8][2];
    #pragma unroll
    for (int r = 0; r < 8; r++){ acc[r][0] = 0ull; acc[r][1] = 0ull; }

    #pragma unroll 1
    for (int kt = 0; kt < 8; kt++){
        __syncthreads();
        #pragma unroll
        for (int i = 0; i < 2; i++){
            int f = t + 256 * i;
            int k = f >> 5, c4 = f & 31;
            *(float4*)&sw[k * 128 + c4 * 4] =
                __ldg((const float4*)(W + (size_t)(kt * 16 + k) * COUT + cb + c4 * 4));
        }
        __syncthreads();
        #pragma unroll
        for (int k = 0; k < 16; k++){
            int kk = kt * 16 + k;
            float4 xa = *(const float4*)&sxT[kk * 68 + ty * 8];
            float4 xb = *(const float4*)&sxT[kk * 68 + ty * 8 + 4];
            float4 wv = *(const float4*)&sw[k * 128 + tx * 4];
            ull w01 = packf2(wv.x, wv.y);
            ull w23 = packf2(wv.z, wv.w);
            float xs[8] = {xa.x, xa.y, xa.z, xa.w, xb.x, xb.y, xb.z, xb.w};
            #pragma unroll
            for (int r = 0; r < 8; r++){
                ull x2 = pack2(xs[r]);
                acc[r][0] = fma2(x2, w01, acc[r][0]);
                acc[r][1] = fma2(x2, w23, acc[r][1]);
            }
        }
    }

    float4 bv = __ldg((const float4*)(B + cb + tx * 4));
    #pragma unroll
    for (int r = 0; r < 8; r++){
        int row = row0 + ty * 8 + r;
        if (row < n){
            float2 p0 = unpack2(acc[r][0]);
            float2 p1 = unpack2(acc[r][1]);
            float4 o = make_float4(p0.x + bv.x, p0.y + bv.y, p1.x + bv.z, p1.y + bv.w);
            *(float4*)(Y + (size_t)row * COUT + cb + tx * 4) = o;
        }
    }
}

// ---------------- fused GATv2 edge pass -------------------------------------
// One warp per (node, 128-column slice). blockIdx.y selects the slice (layer 2
// has 2 slices; softmax is per-head so slices are fully independent).
// 4-edge unrolled mainloop: each We row is LDS'd once per 4 edges (amortizes
// the smem bandwidth that bound the previous version). VPT=4 channels/lane.
// CTOT: row stride of xl/xr; LPH: lanes per head (8 for CH=32, 16 for CH=64).
// MEAN: atomicAdd 0.25*(acc/l) into pre-zeroed out (bias+relu applied in pool).
template<int CTOT, int LPH, bool MEAN>
__global__ void __launch_bounds__(128) gat_edge(const float* __restrict__ xl,
                                                const float* __restrict__ xr,
                                                const float* __restrict__ We,
                                                const float* __restrict__ att,
                                                const float* __restrict__ bias,
                                                const float* __restrict__ eattr,
                                                const int* __restrict__ rowptr,
                                                const int2* __restrict__ se,
                                                float* __restrict__ out, int n){
    constexpr int CSUB = 128;
    const int col0 = blockIdx.y * CSUB;

    __shared__ float sWe[16 * CSUB];
    for (int idx = threadIdx.x; idx < 16 * CSUB / 4; idx += 128){
        int k = idx >> 5, c4 = idx & 31;
        ((float4*)sWe)[idx] = __ldg((const float4*)(We + (size_t)k * CTOT + col0 + c4 * 4));
    }
    __syncthreads();

    int warp = threadIdx.x >> 5;
    int lane = threadIdx.x & 31;
    int node = blockIdx.x * 4 + warp;
    if (node >= n) return;

    const float LOG2E = 1.4426950408889634f;
    float4 at4 = __ldg((const float4*)(att + col0 + lane * 4));
    float atv[4] = {at4.x * LOG2E, at4.y * LOG2E, at4.z * LOG2E, at4.w * LOG2E};
    float4 xr4 = __ldg((const float4*)(xr + (size_t)node * CTOT + col0 + lane * 4));
    ull xrv2[2] = {packf2(xr4.x, xr4.y), packf2(xr4.z, xr4.w)};

    float l = 0.f;
    ull acc2[2] = {0ull, 0ull};
    ull sa2[8];
    #pragma unroll
    for (int j = 0; j < 8; j++) sa2[j] = 0ull;

    const int start = rowptr[node], endi = rowptr[node + 1];
    const float* wbase = sWe + lane * 4;

    int i = start;
    // ---- 4-edge unrolled mainloop ----
    for (; i + 4 <= endi; i += 4){
        const float* eap[4];
        const float* xpp[4];
        #pragma unroll
        for (int e = 0; e < 4; e++){
            int2 pr = __ldg(se + i + e);
            eap[e] = eattr + (size_t)pr.y * 16;
            xpp[e] = xl + (size_t)pr.x * CTOT + col0 + lane * 4;
        }
        float4 xv[4];
        #pragma unroll
        for (int e = 0; e < 4; e++) xv[e] = __ldg((const float4*)xpp[e]);

        ull e2[4][2];
        #pragma unroll
        for (int e = 0; e < 4; e++){
            e2[e][0] = add2(packf2(xv[e].x, xv[e].y), xrv2[0]);
            e2[e][1] = add2(packf2(xv[e].z, xv[e].w), xrv2[1]);
        }

        #pragma unroll
        for (int kt = 0; kt < 4; kt++){
            float4 aa[4];
            #pragma unroll
            for (int e = 0; e < 4; e++) aa[e] = __ldg((const float4*)(eap[e] + kt * 4));
            #pragma unroll
            for (int e = 0; e < 4; e++){
                sa2[kt * 2 + 0] = add2(sa2[kt * 2 + 0], packf2(aa[e].x, aa[e].y));
                sa2[kt * 2 + 1] = add2(sa2[kt * 2 + 1], packf2(aa[e].z, aa[e].w));
            }
            #pragma unroll
            for (int k = 0; k < 4; k++){
                ulonglong2 w = *(const ulonglong2*)(wbase + (kt * 4 + k) * CSUB);
                #pragma unroll
                for (int e = 0; e < 4; e++){
                    float av = (k == 0) ? aa[e].x : (k == 1) ? aa[e].y :
                               (k == 2) ? aa[e].z : aa[e].w;
                    ull a2 = pack2(av);
                    e2[e][0] = fma2(a2, w.x, e2[e][0]);
                    e2[e][1] = fma2(a2, w.y, e2[e][1]);
                }
            }
        }

        float pv[4];
        #pragma unroll
        for (int e = 0; e < 4; e++){
            float2 z0 = unpack2(e2[e][0]);
            float2 z1 = unpack2(e2[e][1]);
            float part;
            float a0 = fmaxf(z0.x, 0.2f * z0.x);
            float a1 = fmaxf(z0.y, 0.2f * z0.y);
            float a2_ = fmaxf(z1.x, 0.2f * z1.x);
            float a3 = fmaxf(z1.y, 0.2f * z1.y);
            part = a0 * atv[0];
            part = fmaf(a1, atv[1], part);
            part = fmaf(a2_, atv[2], part);
            part = fmaf(a3, atv[3], part);
            part += __shfl_xor_sync(0xffffffffu, part, 1);
            part += __shfl_xor_sync(0xffffffffu, part, 2);
            part += __shfl_xor_sync(0xffffffffu, part, 4);
            if (LPH == 16) part += __shfl_xor_sync(0xffffffffu, part, 8);
            pv[e] = exp2f(part);
        }
        l += (pv[0] + pv[1]) + (pv[2] + pv[3]);
        #pragma unroll
        for (int e = 0; e < 4; e++){
            ull p2 = pack2(pv[e]);
            acc2[0] = fma2(p2, packf2(xv[e].x, xv[e].y), acc2[0]);
            acc2[1] = fma2(p2, packf2(xv[e].z, xv[e].w), acc2[1]);
        }
    }

    // ---- single-edge path (remainder + self loop) ----
    auto ONE = [&](const float (&aaf)[16], float4 xv){
        ull ea0 = add2(packf2(xv.x, xv.y), xrv2[0]);
        ull ea1 = add2(packf2(xv.z, xv.w), xrv2[1]);
        #pragma unroll
        for (int k = 0; k < 16; k++){
            ulonglong2 w = *(const ulonglong2*)(wbase + k * CSUB);
            ull a2 = pack2(aaf[k]);
            ea0 = fma2(a2, w.x, ea0);
            ea1 = fma2(a2, w.y, ea1);
        }
        float2 z0 = unpack2(ea0), z1 = unpack2(ea1);
        float a0 = fmaxf(z0.x, 0.2f * z0.x);
        float a1 = fmaxf(z0.y, 0.2f * z0.y);
        float a2_ = fmaxf(z1.x, 0.2f * z1.x);
        float a3 = fmaxf(z1.y, 0.2f * z1.y);
        float part = a0 * atv[0];
        part = fmaf(a1, atv[1], part);
        part = fmaf(a2_, atv[2], part);
        part = fmaf(a3, atv[3], part);
        part += __shfl_xor_sync(0xffffffffu, part, 1);
        part += __shfl_xor_sync(0xffffffffu, part, 2);
        part += __shfl_xor_sync(0xffffffffu, part, 4);
        if (LPH == 16) part += __shfl_xor_sync(0xffffffffu, part, 8);
        float p = exp2f(part);
        l += p;
        ull p2 = pack2(p);
        acc2[0] = fma2(p2, packf2(xv.x, xv.y), acc2[0]);
        acc2[1] = fma2(p2, packf2(xv.z, xv.w), acc2[1]);
    };

    for (; i < endi; i++){
        int2 pr = __ldg(se + i);
        const float* ea = eattr + (size_t)pr.y * 16;
        float aaf[16];
        #pragma unroll
        for (int p = 0; p < 4; p++){
            float4 a4 = __ldg((const float4*)(ea + p * 4));
            aaf[p * 4 + 0] = a4.x; aaf[p * 4 + 1] = a4.y;
            aaf[p * 4 + 2] = a4.z; aaf[p * 4 + 3] = a4.w;
            sa2[p * 2 + 0] = add2(sa2[p * 2 + 0], packf2(a4.x, a4.y));
            sa2[p * 2 + 1] = add2(sa2[p * 2 + 1], packf2(a4.z, a4.w));
        }
        float4 xv = __ldg((const float4*)(xl + (size_t)pr.x * CTOT + col0 + lane * 4));
        ONE(aaf, xv);
    }

    {   // self loop: mean of incoming attrs, xl of self
        float invd = 1.f / (float)max(endi - start, 1);
        float aaf[16];
        #pragma unroll
        for (int j = 0; j < 8; j++){
            float2 v = unpack2(sa2[j]);
            aaf[2 * j]     = v.x * invd;
            aaf[2 * j + 1] = v.y * invd;
        }
        float4 xv = __ldg((const float4*)(xl + (size_t)node * CTOT + col0 + lane * 4));
        ONE(aaf, xv);
    }

    float inv = 1.f / (l + 1e-16f);
    float2 r0 = unpack2(acc2[0]);
    float2 r1 = unpack2(acc2[1]);
    float o0 = r0.x * inv, o1 = r0.y * inv, o2 = r1.x * inv, o3 = r1.y * inv;

    if (!MEAN){
        float4 bo = __ldg((const float4*)(bias + col0 + lane * 4));
        float4 ov;
        ov.x = fmaxf(o0 + bo.x, 0.f);
        ov.y = fmaxf(o1 + bo.y, 0.f);
        ov.z = fmaxf(o2 + bo.z, 0.f);
        ov.w = fmaxf(o3 + bo.w, 0.f);
        *(float4*)(out + (size_t)node * CTOT + col0 + lane * 4) = ov;
    } else {
        // combine the 2 heads in this warp, then atomically add 1/4-scaled
        o0 += __shfl_xor_sync(0xffffffffu, o0, 16);
        o1 += __shfl_xor_sync(0xffffffffu, o1, 16);
        o2 += __shfl_xor_sync(0xffffffffu, o2, 16);
        o3 += __shfl_xor_sync(0xffffffffu, o3, 16);
        if (lane < 16){
            float* op = out + (size_t)node * 64 + lane * 4;
            atomicAdd(op + 0, 0.25f * o0);
            atomicAdd(op + 1, 0.25f * o1);
            atomicAdd(op + 2, 0.25f * o2);
            atomicAdd(op + 3, 0.25f * o3);
        }
    }
}

// ---------------- global mean pool (applies layer-3 bias + relu) -------------
__device__ __forceinline__ int lowerb(const int* a, int n, int v){
    int lo = 0, hi = n;
    while (lo < hi){ int md = (lo + hi) >> 1; if (a[md] < v) lo = md + 1; else hi = md; }
    return lo;
}

__global__ void pool_k(const float* __restrict__ h3, const int* __restrict__ batch,
                       const float* __restrict__ bof, float* __restrict__ gvec, int n){
    int g = blockIdx.x;
    int lo = lowerb(batch, n, g), hi = lowerb(batch, n, g + 1);
    int t = threadIdx.x;
    int ch = t & 63, rr = t >> 6;
    float b = __ldg(bof + ch);
    float s = 0.f;
    for (int i = lo + rr; i < hi; i += 4)
        s += fmaxf(h3[(size_t)i * 64 + ch] + b, 0.f);
    __shared__ float red[4][64];
    red[rr][ch] = s; __syncthreads();
    if (rr == 0){
        float tot = red[0][ch] + red[1][ch] + red[2][ch] + red[3][ch];
        float c = (float)max(hi - lo, 1);
        gvec[g * 64 + ch] = tot / c;
    }
}

__global__ void final_k(const float* __restrict__ gvec, const float* __restrict__ Wlin,
                        const float* __restrict__ blin, float* __restrict__ out){
    int t = threadIdx.x;
    int g = t >> 4, o = t & 15;
    float s = 0.f;
    #pragma unroll
    for (int k = 0; k < 64; k++) s = fmaf(gvec[g * 64 + k], Wlin[k * 16 + o], s);
    out[t] = s + blin[o];
}

// ---------------- host orchestration ----------------
extern "C" void kernel_launch(void* const* d_in, const int* in_sizes, int n_in,
                              void* d_out, int out_size){
    const float* x     = (const float*)d_in[0];
    const int*   eidx  = (const int*)  d_in[1];
    const int*   batch = (const int*)  d_in[2];
    const float* eattr = (const float*)d_in[3];
    const float* Wl0 = (const float*)d_in[4],  *bl0 = (const float*)d_in[5];
    const float* Wr0 = (const float*)d_in[6],  *br0 = (const float*)d_in[7];
    const float* We0 = (const float*)d_in[8],  *att0= (const float*)d_in[9];
    const float* bo0 = (const float*)d_in[10];
    const float* Wlh = (const float*)d_in[11], *blh = (const float*)d_in[12];
    const float* Wrh = (const float*)d_in[13], *brh = (const float*)d_in[14];
    const float* Weh = (const float*)d_in[15], *atth= (const float*)d_in[16];
    const float* boh = (const float*)d_in[17];
    const float* Wlf = (const float*)d_in[18], *blf = (const float*)d_in[19];
    const float* Wrf = (const float*)d_in[20], *brf = (const float*)d_in[21];
    const float* Wef = (const float*)d_in[22], *attf= (const float*)d_in[23];
    const float* bof = (const float*)d_in[24];
    const float* Wlin= (const float*)d_in[25], *blin= (const float*)d_in[26];

    int N = in_sizes[0] / 128;
    int E = in_sizes[1] / 2;
    const int* src = eidx;
    const int* dst = eidx + E;

    float *xl, *xr, *h1, *h2, *h3, *gvec;
    int *rowptr, *cursor;
    int2 *se;
    cudaGetSymbolAddress((void**)&xl,     g_xl);
    cudaGetSymbolAddress((void**)&xr,     g_xr);
    cudaGetSymbolAddress((void**)&h1,     g_h1);
    cudaGetSymbolAddress((void**)&h2,     g_h2);
    cudaGetSymbolAddress((void**)&h3,     g_h3);
    cudaGetSymbolAddress((void**)&gvec,   g_gvec);
    cudaGetSymbolAddress((void**)&rowptr, g_rowptr);
    cudaGetSymbolAddress((void**)&cursor, g_cursor);
    cudaGetSymbolAddress((void**)&se,     g_se);

    size_t dsmem = (size_t)(N + 1 + 1024) * sizeof(int);
    cudaFuncSetAttribute(degscan_k, cudaFuncAttributeMaxDynamicSharedMemorySize,
                         (int)dsmem);

    dim3 gA(1, (N + 63) / 64, 2), gB(2, (N + 63) / 64, 2);
    dim3 ge1((N + 3) / 4, 1), ge2((N + 3) / 4, 2);

    // h3 must be zero for the MEAN layer's atomic accumulation (memset node,
    // not a kernel launch; keeps gat_edge L0 at kernel index 3 for ncu)
    cudaMemsetAsync(h3, 0, (size_t)N * 64 * sizeof(float));

    degscan_k<<<1, 1024, dsmem>>>(dst, E, N, rowptr, cursor);                       // 0
    scatter_k<<<(E + 255) / 256, 256>>>(src, dst, cursor, se, E);                   // 1
    gemm2<128><<<gA, 256>>>(x, Wl0, bl0, Wr0, br0, xl, xr, N);                      // 2
    gat_edge<128, 8, false><<<ge1, 128>>>(xl, xr, We0, att0, bo0, eattr,
                                          rowptr, se, h1, N);                       // 3 (profiled)
    gemm2<128><<<gA, 256>>>(h1, Wlh, blh, Wrh, brh, xl, xr, N);                     // 4
    gat_edge<128, 8, false><<<ge1, 128>>>(xl, xr, Weh, atth, boh, eattr,
                                          rowptr, se, h2, N);                       // 5
    gemm2<256><<<gB, 256>>>(h2, Wlf, blf, Wrf, brf, xl, xr, N);                     // 6
    gat_edge<256, 16, true><<<ge2, 128>>>(xl, xr, Wef, attf, bof, eattr,
                                          rowptr, se, h3, N);                       // 7
    pool_k <<<64, 256>>>(h3, batch, bof, gvec, N);                                  // 8
    final_k<<<1, 1024>>>(gvec, Wlin, blin, (float*)d_out);                          // 9
}